// round 16
// baseline (speedup 1.0000x reference)
#include <cuda_runtime.h>
#include <cuda_bf16.h>
#include <cuda_fp16.h>
#include <cstdint>

#define NROWS  131072
#define DDIM   64
#define KCODES 1024
#define BM2    256          // rows per block in k_main
#define MARGIN 0.05f
#define FB_ROWS 32
#define FB_BPITCH 132
#define NREP   4            // g_isum replicas (contention reduction)

// ---------------- device scratch ----------------
__device__ float g_cnorm[KCODES];
__device__ float g_counts[KCODES];
__device__ float g_isum[NREP][DDIM * KCODES];   // D-MAJOR replicas: [rep][d][code]
__device__ int   g_idx[NROWS];
__device__ float g_cbT[KCODES * DDIM];
__device__ __align__(16) __half g_cbh[KCODES * DDIM];  // [code][dim] fp16 codebook
__device__ int   g_nflag;
__device__ int   g_flag[NROWS];
__device__ unsigned long long g_pack[NROWS];

__device__ __forceinline__ uint32_t smem_u32(const void* p) {
    uint32_t a;
    asm("{ .reg .u64 t; cvta.to.shared.u64 t, %1; cvt.u32.u64 %0, t; }" : "=r"(a) : "l"(p));
    return a;
}
__device__ __forceinline__ uint32_t f32_sortable(float f) {
    uint32_t u = __float_as_uint(f);
    return (u & 0x80000000u) ? ~u : (u | 0x80000000u);
}

// ---------------- kernel 0: init scratch + codebook fp16 + norms ----------
__global__ void k_init(const float* __restrict__ cb, float* __restrict__ loss_slot) {
    int t = blockIdx.x * blockDim.x + threadIdx.x;   // 128 x 1024 = 131072
    g_pack[t] = 0xFFFFFFFFFFFFFFFFull;
    if (t < DDIM * KCODES) {
#pragma unroll
        for (int r = 0; r < NREP; r++) g_isum[r][t] = 0.0f;
    }
    if (t < KCODES) {
        g_counts[t] = 0.0f;
        float s = 0.0f;
#pragma unroll
        for (int d = 0; d < DDIM; d++) {
            float v = cb[d * KCODES + t];
            s = fmaf(v, v, s);
            g_cbh[t * DDIM + d] = __float2half_rn(v);
        }
        g_cnorm[t] = s;
    }
    if (t == 0) { *loss_slot = 0.0f; g_nflag = 0; }
}

// ---------------- kernel 1: fp16 mma argmin (group-min epilogue) + fused scatter ----
#define SMA_BYTES 36864
#define SMB_BYTES 147456
#define SMC_BYTES 4096
#define SMI_BYTES 1024
#define SM_MAIN_TOT (SMA_BYTES + SMB_BYTES + SMC_BYTES + SMI_BYTES)

#define MERGE(b, s, i, m) do {                                     \
    float ob = __shfl_xor_sync(0xffffffffu, (b), (m));             \
    float os = __shfl_xor_sync(0xffffffffu, (s), (m));             \
    int   oi = __shfl_xor_sync(0xffffffffu, (i), (m));             \
    float ns = fminf(fminf((s), os), fmaxf((b), ob));              \
    if (ob < (b) || (ob == (b) && oi < (i))) { (b) = ob; (i) = oi; } \
    (s) = ns;                                                      \
} while (0)

// quad-cooperative recovery: recompute the winning 4-code group's distances
// from smem, pick argmin (ascending-code tie-break), return best/second/idx.
__device__ __forceinline__ void recover_group(
    const char* Abf, const char* Bbf, const float* s_cn,
    int lane, int arow, int pid,
    float& best, float& second, int& bidx)
{
    int q = lane & 3;
    int gbase = (pid >> 2) * 16 + (pid & 3) * 2;
    const int codes[4] = {gbase, gbase + 1, gbase + 8, gbase + 9};
    const __half2* ap = (const __half2*)(Abf + arow * 144 + q * 32);
    float s[4] = {0.f, 0.f, 0.f, 0.f};
#pragma unroll
    for (int c = 0; c < 4; c++) {
        const __half2* bp = (const __half2*)(Bbf + codes[c] * 144 + q * 32);
        float acc = 0.f;
#pragma unroll
        for (int i = 0; i < 8; i++) {
            float2 a2 = __half22float2(ap[i]);
            float2 b2 = __half22float2(bp[i]);
            acc = fmaf(a2.x, b2.x, acc);
            acc = fmaf(a2.y, b2.y, acc);
        }
        s[c] = acc;
    }
#pragma unroll
    for (int c = 0; c < 4; c++) {
        s[c] += __shfl_xor_sync(0xffffffffu, s[c], 1);
        s[c] += __shfl_xor_sync(0xffffffffu, s[c], 2);
    }
    best = 3.4e38f; second = 3.4e38f; bidx = codes[0];
#pragma unroll
    for (int c = 0; c < 4; c++) {
        float d = fmaf(-2.0f, s[c], s_cn[codes[c]]);
        if (d < best) { second = best; best = d; bidx = codes[c]; }
        else if (d < second) second = d;
    }
}

extern __shared__ char smemc[];
__global__ void __launch_bounds__(512, 1)
k_main(const float* __restrict__ x) {
    char* Abf = smemc;                       // row stride 144 B (72 fp16)
    char* Bbf = smemc + SMA_BYTES;           // row stride 144 B
    float* s_cn = (float*)(smemc + SMA_BYTES + SMB_BYTES);
    int* s_code = (int*)(smemc + SMA_BYTES + SMB_BYTES + SMC_BYTES);

    const int tid  = threadIdx.x;
    const int lane = tid & 31;
    const int wid  = tid >> 5;
    const int rowbase = blockIdx.x * BM2;

    {
        const uint4* gB = (const uint4*)g_cbh;
#pragma unroll
        for (int i = 0; i < 16; i++) {
            int v = tid + i * 512;
            int rc = v >> 3, d8 = v & 7;
            *(uint4*)(Bbf + rc * 144 + d8 * 16) = gB[v];
        }
    }
#pragma unroll
    for (int i = 0; i < 2; i++) s_cn[tid + i * 512] = g_cnorm[tid + i * 512];

    {
        const float4* xg = (const float4*)(x + (size_t)rowbase * DDIM);
#pragma unroll
        for (int i = 0; i < 8; i++) {
            int v = tid + i * 512;
            int r = v >> 4, d4 = (v & 15) << 2;
            float4 f = xg[v];
            uint32_t lo = ((uint32_t)__half_as_ushort(__float2half_rn(f.y)) << 16)
                        |  (uint32_t)__half_as_ushort(__float2half_rn(f.x));
            uint32_t hi = ((uint32_t)__half_as_ushort(__float2half_rn(f.w)) << 16)
                        |  (uint32_t)__half_as_ushort(__float2half_rn(f.z));
            *(uint2*)(Abf + r * 144 + d4 * 2) = make_uint2(lo, hi);
        }
    }
    __syncthreads();

    const uint32_t Abase = smem_u32(Abf);
    const uint32_t Bbase = smem_u32(Bbf);
    const int m0 = wid * 16;

    uint32_t a[4][4];
    {
        uint32_t ar = Abase + (uint32_t)(m0 + (lane & 15)) * 144 + (uint32_t)(lane >> 4) * 16;
#pragma unroll
        for (int kt = 0; kt < 4; kt++) {
            asm volatile("ldmatrix.sync.aligned.m8n8.x4.shared.b16 {%0,%1,%2,%3}, [%4];"
                : "=r"(a[kt][0]), "=r"(a[kt][1]), "=r"(a[kt][2]), "=r"(a[kt][3])
                : "r"(ar + kt * 32));
        }
    }

    // group-min tracking: m1/m2/pid per row half (lo: row m0+lane/4, hi: +8)
    float m1l = 3.4e38f, m2l = 3.4e38f, m1h = 3.4e38f, m2h = 3.4e38f;
    int   pl = 0, ph = 0;
    const uint32_t baddr0 = Bbase + (uint32_t)(lane & 7) * 144 + (uint32_t)(lane >> 3) * 16;
    const int q4 = lane & 3;

#define MMA4(c0_, c1_, c2_, c3_, B0_, B1_, B2_, B3_, B4_, B5_, B6_, B7_)               \
    asm volatile("mma.sync.aligned.m16n8k16.row.col.f32.f16.f16.f32 "                  \
        "{%0,%1,%2,%3}, {%4,%5,%6,%7}, {%8,%9}, {%0,%1,%2,%3};"                        \
        : "+f"(c0_), "+f"(c1_), "+f"(c2_), "+f"(c3_)                                   \
        : "r"(a[0][0]), "r"(a[0][1]), "r"(a[0][2]), "r"(a[0][3]), "r"(B0_), "r"(B1_)); \
    asm volatile("mma.sync.aligned.m16n8k16.row.col.f32.f16.f16.f32 "                  \
        "{%0,%1,%2,%3}, {%4,%5,%6,%7}, {%8,%9}, {%0,%1,%2,%3};"                        \
        : "+f"(c0_), "+f"(c1_), "+f"(c2_), "+f"(c3_)                                   \
        : "r"(a[1][0]), "r"(a[1][1]), "r"(a[1][2]), "r"(a[1][3]), "r"(B2_), "r"(B3_)); \
    asm volatile("mma.sync.aligned.m16n8k16.row.col.f32.f16.f16.f32 "                  \
        "{%0,%1,%2,%3}, {%4,%5,%6,%7}, {%8,%9}, {%0,%1,%2,%3};"                        \
        : "+f"(c0_), "+f"(c1_), "+f"(c2_), "+f"(c3_)                                   \
        : "r"(a[2][0]), "r"(a[2][1]), "r"(a[2][2]), "r"(a[2][3]), "r"(B4_), "r"(B5_)); \
    asm volatile("mma.sync.aligned.m16n8k16.row.col.f32.f16.f16.f32 "                  \
        "{%0,%1,%2,%3}, {%4,%5,%6,%7}, {%8,%9}, {%0,%1,%2,%3};"                        \
        : "+f"(c0_), "+f"(c1_), "+f"(c2_), "+f"(c3_)                                   \
        : "r"(a[3][0]), "r"(a[3][1]), "r"(a[3][2]), "r"(a[3][3]), "r"(B6_), "r"(B7_))

#pragma unroll 2
    for (int g = 0; g < 64; g++) {          // 2 nt per iteration
        uint32_t ad0 = baddr0 + (uint32_t)(2 * g) * (8 * 144);
        uint32_t ad1 = ad0 + 8 * 144;
        uint32_t p0, p1, p2, p3, p4, p5, p6, p7;
        uint32_t r0, r1, r2, r3, r4, r5, r6, r7;
        asm volatile("ldmatrix.sync.aligned.m8n8.x4.shared.b16 {%0,%1,%2,%3}, [%4];"
            : "=r"(p0), "=r"(p1), "=r"(p2), "=r"(p3) : "r"(ad0));
        asm volatile("ldmatrix.sync.aligned.m8n8.x4.shared.b16 {%0,%1,%2,%3}, [%4];"
            : "=r"(p4), "=r"(p5), "=r"(p6), "=r"(p7) : "r"(ad0 + 64));
        asm volatile("ldmatrix.sync.aligned.m8n8.x4.shared.b16 {%0,%1,%2,%3}, [%4];"
            : "=r"(r0), "=r"(r1), "=r"(r2), "=r"(r3) : "r"(ad1));
        asm volatile("ldmatrix.sync.aligned.m8n8.x4.shared.b16 {%0,%1,%2,%3}, [%4];"
            : "=r"(r4), "=r"(r5), "=r"(r6), "=r"(r7) : "r"(ad1 + 64));

        float c0 = 0.f, c1 = 0.f, c2 = 0.f, c3 = 0.f;
        float e0 = 0.f, e1 = 0.f, e2 = 0.f, e3 = 0.f;
        MMA4(c0, c1, c2, c3, p0, p1, p2, p3, p4, p5, p6, p7);
        MMA4(e0, e1, e2, e3, r0, r1, r2, r3, r4, r5, r6, r7);

        int c0a = g * 16 + q4 * 2;
        float2 cnA = *(const float2*)(s_cn + c0a);
        float2 cnB = *(const float2*)(s_cn + c0a + 8);
        float d0 = fmaf(-2.0f, c0, cnA.x);
        float d1 = fmaf(-2.0f, c1, cnA.y);
        float d2 = fmaf(-2.0f, c2, cnA.x);
        float d3 = fmaf(-2.0f, c3, cnA.y);
        float d4 = fmaf(-2.0f, e0, cnB.x);
        float d5 = fmaf(-2.0f, e1, cnB.y);
        float d6 = fmaf(-2.0f, e2, cnB.x);
        float d7 = fmaf(-2.0f, e3, cnB.y);

        float mlo = fminf(fminf(d0, d1), fminf(d4, d5));
        float mhi = fminf(fminf(d2, d3), fminf(d6, d7));
        int pid = g * 4 + q4;
        if (mlo < m1l) { m2l = m1l; m1l = mlo; pl = pid; } else m2l = fminf(m2l, mlo);
        if (mhi < m1h) { m2h = m1h; m1h = mhi; ph = pid; } else m2h = fminf(m2h, mhi);
    }
#undef MMA4

    // quad merge
    MERGE(m1l, m2l, pl, 1); MERGE(m1l, m2l, pl, 2);
    MERGE(m1h, m2h, ph, 1); MERGE(m1h, m2h, ph, 2);

    // recovery: recompute winning group exactly (same fp16 inputs) per row
    const int arow_lo = m0 + (lane >> 2);
    const int arow_hi = arow_lo + 8;
    float bestl, secl_g, besth, sech_g;
    int   il, ih;
    recover_group(Abf, Bbf, s_cn, lane, arow_lo, pl, bestl, secl_g, il);
    recover_group(Abf, Bbf, s_cn, lane, arow_hi, ph, besth, sech_g, ih);
    float secl = fminf(m2l, secl_g);
    float sech = fminf(m2h, sech_g);

    if ((lane & 3) == 0) {
        int g = lane >> 2;
        int row_lo = rowbase + m0 + g;
        int row_hi = row_lo + 8;
        g_idx[row_lo] = il;
        g_idx[row_hi] = ih;
        bool flag_lo = (secl - bestl < MARGIN);
        bool flag_hi = (sech - besth < MARGIN);
        s_code[m0 + g]     = flag_lo ? -1 : il;
        s_code[m0 + g + 8] = flag_hi ? -1 : ih;
        if (flag_lo) { int p = atomicAdd(&g_nflag, 1); g_flag[p] = row_lo; }
        if (flag_hi) { int p = atomicAdd(&g_nflag, 1); g_flag[p] = row_hi; }
    }
    __syncthreads();

    // fused scatter for NON-flagged rows of this block
#pragma unroll
    for (int it = 0; it < 2; it++) {
        int task = tid + it * 512;          // 1024 tasks = 256 rows x 4 quarters
        int r = task >> 2, q = task & 3;
        int code = s_code[r];
        if (code >= 0) {
            int row = rowbase + r;
            if (q == 0) atomicAdd(&g_counts[code], 1.0f);
            float* isum = g_isum[row & (NREP - 1)];
            const float4* xr = (const float4*)(x + (size_t)row * DDIM + q * 16);
#pragma unroll
            for (int j = 0; j < 4; j++) {
                float4 f = xr[j];
                int d = q * 16 + j * 4;
                atomicAdd(&isum[(d + 0) * KCODES + code], f.x);
                atomicAdd(&isum[(d + 1) * KCODES + code], f.y);
                atomicAdd(&isum[(d + 2) * KCODES + code], f.z);
                atomicAdd(&isum[(d + 3) * KCODES + code], f.w);
            }
        }
    }
}

// ---------------- kernel 1b: exact fp32 re-solve, 32 rows x 128-code eighth ----
__global__ void __launch_bounds__(256)
k_fallback(const float* __restrict__ x, const float* __restrict__ cb) {
    float* As = (float*)smemc;                 // [64][FB_ROWS]  (8 KB)
    float* Bs = As + DDIM * FB_ROWS;           // [64][FB_BPITCH] (33.8 KB)

    const int tid = threadIdx.x;
    const int tx = tid & 15;
    const int ty = tid >> 4;
    const int eighth = blockIdx.x & 7;
    const int tile0  = blockIdx.x >> 3;
    const int ntiles = gridDim.x >> 3;
    const int count = g_nflag;
    const int kc = eighth * 128;

    for (int base = tile0 * FB_ROWS; base < count; base += ntiles * FB_ROWS) {
        __syncthreads();
#pragma unroll
        for (int i = 0; i < 2; i++) {
            int v = tid + i * 256;
            int r = v >> 4, d4 = (v & 15) << 2;
            int fi = base + r; if (fi > count - 1) fi = count - 1;
            int fr = g_flag[fi];
            float4 t4 = *(const float4*)(x + (size_t)fr * DDIM + d4);
            As[(d4 + 0) * FB_ROWS + r] = t4.x;
            As[(d4 + 1) * FB_ROWS + r] = t4.y;
            As[(d4 + 2) * FB_ROWS + r] = t4.z;
            As[(d4 + 3) * FB_ROWS + r] = t4.w;
        }
#pragma unroll
        for (int i = 0; i < 8; i++) {
            int v = tid + i * 256;
            int d = v >> 5, c4 = (v & 31) << 2;
            *(float4*)(Bs + d * FB_BPITCH + c4) = *(const float4*)(cb + d * KCODES + kc + c4);
        }
        __syncthreads();

        float best0 = 3.4e38f, best1 = 3.4e38f;
        int   bidx0 = 0, bidx1 = 0;
        float acc0[8], acc1[8];
#pragma unroll
        for (int j = 0; j < 8; j++) { acc0[j] = 0.0f; acc1[j] = 0.0f; }

#pragma unroll 16
        for (int d = 0; d < DDIM; d++) {
            float a0 = As[d * FB_ROWS + ty];
            float a1 = As[d * FB_ROWS + ty + 16];
            float4 q0 = *(const float4*)(Bs + d * FB_BPITCH + tx * 8);
            float4 q1 = *(const float4*)(Bs + d * FB_BPITCH + tx * 8 + 4);
            acc0[0] = fmaf(a0, q0.x, acc0[0]);
            acc0[1] = fmaf(a0, q0.y, acc0[1]);
            acc0[2] = fmaf(a0, q0.z, acc0[2]);
            acc0[3] = fmaf(a0, q0.w, acc0[3]);
            acc0[4] = fmaf(a0, q1.x, acc0[4]);
            acc0[5] = fmaf(a0, q1.y, acc0[5]);
            acc0[6] = fmaf(a0, q1.z, acc0[6]);
            acc0[7] = fmaf(a0, q1.w, acc0[7]);
            acc1[0] = fmaf(a1, q0.x, acc1[0]);
            acc1[1] = fmaf(a1, q0.y, acc1[1]);
            acc1[2] = fmaf(a1, q0.z, acc1[2]);
            acc1[3] = fmaf(a1, q0.w, acc1[3]);
            acc1[4] = fmaf(a1, q1.x, acc1[4]);
            acc1[5] = fmaf(a1, q1.y, acc1[5]);
            acc1[6] = fmaf(a1, q1.z, acc1[6]);
            acc1[7] = fmaf(a1, q1.w, acc1[7]);
        }

#pragma unroll
        for (int j = 0; j < 8; j++) {
            int kidx = kc + tx * 8 + j;
            float cn = __ldg(&g_cnorm[kidx]);
            float dist0 = fmaf(-2.0f, acc0[j], cn);
            float dist1 = fmaf(-2.0f, acc1[j], cn);
            if (dist0 < best0) { best0 = dist0; bidx0 = kidx; }
            if (dist1 < best1) { best1 = dist1; bidx1 = kidx; }
        }

#pragma unroll
        for (int m = 1; m < 16; m <<= 1) {
            float ob = __shfl_xor_sync(0xffffffffu, best0, m);
            int   oi = __shfl_xor_sync(0xffffffffu, bidx0, m);
            if (ob < best0 || (ob == best0 && oi < bidx0)) { best0 = ob; bidx0 = oi; }
            float ob1 = __shfl_xor_sync(0xffffffffu, best1, m);
            int   oi1 = __shfl_xor_sync(0xffffffffu, bidx1, m);
            if (ob1 < best1 || (ob1 == best1 && oi1 < bidx1)) { best1 = ob1; bidx1 = oi1; }
        }
        if (tx == 0) {
            if (base + ty < count) {
                unsigned long long key =
                    ((unsigned long long)f32_sortable(best0) << 32) | (uint32_t)bidx0;
                atomicMin(&g_pack[g_flag[base + ty]], key);
            }
            if (base + ty + 16 < count) {
                unsigned long long key =
                    ((unsigned long long)f32_sortable(best1) << 32) | (uint32_t)bidx1;
                atomicMin(&g_pack[g_flag[base + ty + 16]], key);
            }
        }
        __syncthreads();
    }
}

// ---------------- kernel 1c: scatter for FLAGGED rows only ----------------
__global__ void k_scatter_fl(const float* __restrict__ x) {
    int total = g_nflag * 4;
    for (int t = blockIdx.x * 256 + threadIdx.x; t < total; t += gridDim.x * 256) {
        int fi = t >> 2, q = t & 3;
        int row = g_flag[fi];
        int code = (int)(uint32_t)(g_pack[row] & 0xFFFFFFFFull);
        if (q == 0) {
            g_idx[row] = code;              // final index for k_quant
            atomicAdd(&g_counts[code], 1.0f);
        }
        float* isum = g_isum[row & (NREP - 1)];
        const float4* xr = (const float4*)(x + (size_t)row * DDIM + q * 16);
#pragma unroll
        for (int j = 0; j < 4; j++) {
            float4 f = xr[j];
            int d = q * 16 + j * 4;
            atomicAdd(&isum[(d + 0) * KCODES + code], f.x);
            atomicAdd(&isum[(d + 1) * KCODES + code], f.y);
            atomicAdd(&isum[(d + 2) * KCODES + code], f.z);
            atomicAdd(&isum[(d + 3) * KCODES + code], f.w);
        }
    }
}

// ---------------- kernel 2: fused EMA stats + codebook update ----------------
__global__ void k_upd(const float* __restrict__ ema_cs,
                      const float* __restrict__ ema_sum,
                      float* __restrict__ out_cs,
                      float* __restrict__ out_sum,
                      float* __restrict__ out_cb) {
    int k = threadIdx.x;
    int d = blockIdx.x;
    float cs = fmaf(0.99f, ema_cs[k], 0.01f * g_counts[k]);

    __shared__ float red_[32];
    __shared__ float s_n;
    float s = cs;
#pragma unroll
    for (int m = 16; m >= 1; m >>= 1) s += __shfl_xor_sync(0xffffffffu, s, m);
    int lane = k & 31, warp = k >> 5;
    if (lane == 0) red_[warp] = s;
    __syncthreads();
    if (warp == 0) {
        float v = red_[lane];
#pragma unroll
        for (int m = 16; m >= 1; m >>= 1) v += __shfl_xor_sync(0xffffffffu, v, m);
        if (lane == 0) s_n = v;
    }
    __syncthreads();
    float n = s_n;
    float csize = ((cs + 1e-5f) / (n + KCODES * 1e-5f)) * n;
    if (d == 0) out_cs[k] = cs;

    int e = d * KCODES + k;
    float isum = (g_isum[0][e] + g_isum[1][e]) + (g_isum[2][e] + g_isum[3][e]);
    float num = fmaf(0.99f, ema_sum[e], 0.01f * isum);
    out_sum[e] = num;
    float ncb = num / csize;
    out_cb[e] = ncb;
    g_cbT[k * DDIM + d] = ncb;
}

// ---------------- kernel 3: quantize + loss ----------------
__global__ void k_quant(const float* __restrict__ x,
                        float* __restrict__ out_q, float* __restrict__ out_loss) {
    int t = blockIdx.x * 256 + threadIdx.x;
    float lsum = 0.0f;
#pragma unroll
    for (int it = 0; it < 2; it++) {
        int e4 = t + it * (4096 * 256);
        int r = e4 >> 4, d4 = (e4 & 15) << 2;
        int code = g_idx[r];
        float4 q4 = *(const float4*)(g_cbT + code * DDIM + d4);
        float4 x4 = *(const float4*)(x + ((size_t)e4 << 2));
        float dx0 = q4.x - x4.x, dx1 = q4.y - x4.y, dx2 = q4.z - x4.z, dx3 = q4.w - x4.w;
        float4 o;
        o.x = x4.x + dx0; o.y = x4.y + dx1; o.z = x4.z + dx2; o.w = x4.w + dx3;
        *(float4*)(out_q + ((size_t)e4 << 2)) = o;
        lsum = fmaf(dx0, dx0, lsum); lsum = fmaf(dx1, dx1, lsum);
        lsum = fmaf(dx2, dx2, lsum); lsum = fmaf(dx3, dx3, lsum);
    }
    __shared__ float red[8];
#pragma unroll
    for (int m = 16; m >= 1; m >>= 1) lsum += __shfl_xor_sync(0xffffffffu, lsum, m);
    int lane = threadIdx.x & 31, warp = threadIdx.x >> 5;
    if (lane == 0) red[warp] = lsum;
    __syncthreads();
    if (warp == 0) {
        float v = (lane < 8) ? red[lane] : 0.0f;
#pragma unroll
        for (int m = 4; m >= 1; m >>= 1) v += __shfl_xor_sync(0xffffffffu, v, m);
        if (lane == 0) atomicAdd(out_loss, v * (1.0f / 8388608.0f));
    }
}

// ---------------- launch ----------------
extern "C" void kernel_launch(void* const* d_in, const int* in_sizes, int n_in,
                              void* d_out, int out_size) {
    const float* x       = (const float*)d_in[0];
    const float* cb      = (const float*)d_in[1];
    const float* ema_cs  = (const float*)d_in[2];
    const float* ema_sum = (const float*)d_in[3];

    float* out      = (float*)d_out;
    float* out_q    = out;
    float* out_loss = out + 8388608;
    float* out_cb   = out_loss + 1;
    float* out_cs   = out_cb + 65536;
    float* out_sum  = out_cs + 1024;

    const int FB_SMEM = (DDIM * FB_ROWS + DDIM * FB_BPITCH) * 4;   // 41984 B
    static bool attr_set = false;
    if (!attr_set) {
        cudaFuncSetAttribute(k_main, cudaFuncAttributeMaxDynamicSharedMemorySize, SM_MAIN_TOT);
        cudaFuncSetAttribute(k_fallback, cudaFuncAttributeMaxDynamicSharedMemorySize, FB_SMEM);
        attr_set = true;
    }

    k_init<<<128, 1024>>>(cb, out_loss);
    k_main<<<NROWS / BM2, 512, SM_MAIN_TOT>>>(x);
    k_fallback<<<2048, 256, FB_SMEM>>>(x, cb);   // 256 tiles x 8 code-eighths
    k_scatter_fl<<<64, 256>>>(x);
    k_upd<<<64, 1024>>>(ema_cs, ema_sum, out_cs, out_sum, out_cb);
    k_quant<<<4096, 256>>>(x, out_q, out_loss);
}